// round 1
// baseline (speedup 1.0000x reference)
#include <cuda_runtime.h>

#define NB 2
#define LD 4800
#define SD 4800
#define CD 256
#define TEMPER 0.1f
#define THRESH 0.2f
#define BORDER 2
#define NEG_INF __int_as_float(0xff800000)

// ---------------- scratch (device globals: allocation-free rule) ----------------
__device__ float g_sim[(size_t)NB * LD * SD];                 // 184.3 MB
__device__ float g_rmax[NB * LD];
__device__ float g_rsum[NB * LD];
__device__ unsigned long long g_cms[NB * SD];                 // packed {max(lo), sum(hi)} per column
__device__ float g_rcmax[NB * LD];                            // row max of conf
__device__ float g_ccmax[NB * SD];                            // col max of conf

// ---------------- helpers ----------------
__device__ __forceinline__ float warpMax(float v) {
    #pragma unroll
    for (int o = 16; o; o >>= 1) v = fmaxf(v, __shfl_xor_sync(0xffffffffu, v, o));
    return v;
}
__device__ __forceinline__ float warpSum(float v) {
    #pragma unroll
    for (int o = 16; o; o >>= 1) v += __shfl_xor_sync(0xffffffffu, v, o);
    return v;
}
__device__ __forceinline__ int warpMinI(int v) {
    #pragma unroll
    for (int o = 16; o; o >>= 1) v = min(v, __shfl_xor_sync(0xffffffffu, v, o));
    return v;
}

__device__ __forceinline__ void atomicMaxFloat(float* addr, float val) {
    unsigned int* ua = (unsigned int*)addr;
    unsigned int old = *ua;
    while (val > __uint_as_float(old)) {
        unsigned int assumed = old;
        old = atomicCAS(ua, assumed, __float_as_uint(val));
        if (old == assumed) break;
    }
}

// combine (m2, s2) into packed running (max, sumexp) pair
__device__ __forceinline__ void atomicCombineMS(unsigned long long* addr, float m2, float s2) {
    unsigned long long old = *addr, assumed;
    do {
        assumed = old;
        float m1 = __uint_as_float((unsigned int)(assumed & 0xffffffffu));
        float s1 = __uint_as_float((unsigned int)(assumed >> 32));
        float nm = fmaxf(m1, m2);
        float ns = s1 * expf(m1 - nm) + s2 * expf(m2 - nm);
        unsigned long long nv =
            ((unsigned long long)__float_as_uint(ns) << 32) | __float_as_uint(nm);
        old = atomicCAS(addr, assumed, nv);
    } while (old != assumed);
}

// ---------------- kernels ----------------
__global__ void k_init() {
    int i = blockIdx.x * blockDim.x + threadIdx.x;
    if (i < NB * SD) {
        g_cms[i] = ((unsigned long long)0u << 32) | 0xff800000u;  // sum=0, max=-inf
        g_ccmax[i] = NEG_INF;
    }
}

// 128x128x32 fp32 SGEMM: sim[n,l,s] = dot(f0[n,l,:], f1[n,s,:]) / (C * T)
#define BM 128
#define BN 128
#define BK 32
__global__ void __launch_bounds__(256) k_gemm(const float* __restrict__ A,
                                              const float* __restrict__ B) {
    __shared__ float As[BK][BM + 4];
    __shared__ float Bs[BK][BN + 4];
    const int n  = blockIdx.z;
    const int m0 = blockIdx.y * BM;
    const int n0 = blockIdx.x * BN;
    const float* Ab = A + (size_t)n * LD * CD;
    const float* Bb = B + (size_t)n * SD * CD;
    const int tid = threadIdx.x;
    const int tx = tid & 15, ty = tid >> 4;

    float acc[8][8];
    #pragma unroll
    for (int i = 0; i < 8; i++)
        #pragma unroll
        for (int j = 0; j < 8; j++) acc[i][j] = 0.f;

    for (int k0 = 0; k0 < CD; k0 += BK) {
        #pragma unroll
        for (int i = 0; i < 4; i++) {
            int f = tid + i * 256;       // 0..1023 float4 slots
            int row = f >> 3;            // 0..127
            int kk  = (f & 7) * 4;       // 0..28
            int gm = m0 + row;
            float4 v = make_float4(0.f, 0.f, 0.f, 0.f);
            if (gm < LD) v = *reinterpret_cast<const float4*>(Ab + (size_t)gm * CD + k0 + kk);
            As[kk + 0][row] = v.x; As[kk + 1][row] = v.y;
            As[kk + 2][row] = v.z; As[kk + 3][row] = v.w;
            int gs = n0 + row;
            float4 w = make_float4(0.f, 0.f, 0.f, 0.f);
            if (gs < SD) w = *reinterpret_cast<const float4*>(Bb + (size_t)gs * CD + k0 + kk);
            Bs[kk + 0][row] = w.x; Bs[kk + 1][row] = w.y;
            Bs[kk + 2][row] = w.z; Bs[kk + 3][row] = w.w;
        }
        __syncthreads();
        #pragma unroll
        for (int k = 0; k < BK; k++) {
            float4 a0 = *reinterpret_cast<const float4*>(&As[k][ty * 8]);
            float4 a1 = *reinterpret_cast<const float4*>(&As[k][ty * 8 + 4]);
            float4 b0 = *reinterpret_cast<const float4*>(&Bs[k][tx * 8]);
            float4 b1 = *reinterpret_cast<const float4*>(&Bs[k][tx * 8 + 4]);
            float a[8] = {a0.x, a0.y, a0.z, a0.w, a1.x, a1.y, a1.z, a1.w};
            float b[8] = {b0.x, b0.y, b0.z, b0.w, b1.x, b1.y, b1.z, b1.w};
            #pragma unroll
            for (int i = 0; i < 8; i++)
                #pragma unroll
                for (int j = 0; j < 8; j++) acc[i][j] = fmaf(a[i], b[j], acc[i][j]);
        }
        __syncthreads();
    }

    const float sc = 1.0f / ((float)CD * TEMPER);
    #pragma unroll
    for (int i = 0; i < 8; i++) {
        int gm = m0 + ty * 8 + i;
        if (gm >= LD) continue;
        float* dst = g_sim + ((size_t)n * LD + gm) * SD;
        #pragma unroll
        for (int j4 = 0; j4 < 2; j4++) {
            int gc = n0 + tx * 8 + j4 * 4;
            if (gc < SD) {
                float4 o;
                o.x = acc[i][j4 * 4 + 0] * sc;
                o.y = acc[i][j4 * 4 + 1] * sc;
                o.z = acc[i][j4 * 4 + 2] * sc;
                o.w = acc[i][j4 * 4 + 3] * sc;
                *reinterpret_cast<float4*>(dst + gc) = o;
            }
        }
    }
}

// per-row max + sumexp in one read (values held in registers)
__global__ void __launch_bounds__(256) k_rowstats() {
    const int row = blockIdx.x;                 // 0 .. NB*LD-1
    const float* r = g_sim + (size_t)row * SD;
    float v[19];
    float m = NEG_INF;
    #pragma unroll
    for (int j = 0; j < 19; j++) {
        int s = threadIdx.x + j * 256;
        v[j] = (s < SD) ? r[s] : NEG_INF;
        m = fmaxf(m, v[j]);
    }
    __shared__ float sred[8];
    float wm = warpMax(m);
    if ((threadIdx.x & 31) == 0) sred[threadIdx.x >> 5] = wm;
    __syncthreads();
    float bm = NEG_INF;
    #pragma unroll
    for (int i = 0; i < 8; i++) bm = fmaxf(bm, sred[i]);
    __syncthreads();

    float sum = 0.f;
    #pragma unroll
    for (int j = 0; j < 19; j++) sum += expf(v[j] - bm);   // padded lanes: exp(-inf)=0
    float ws = warpSum(sum);
    if ((threadIdx.x & 31) == 0) sred[threadIdx.x >> 5] = ws;
    __syncthreads();
    if (threadIdx.x == 0) {
        float t = 0.f;
        #pragma unroll
        for (int i = 0; i < 8; i++) t += sred[i];
        g_rmax[row] = bm;
        g_rsum[row] = t;
    }
}

// column stats: stripes of 256 cols x 600 rows, online (max,sum), CAS-pair combine
#define RCH 600
__global__ void __launch_bounds__(256) k_colstats() {
    const int n = blockIdx.z;
    const int c = blockIdx.x * 256 + threadIdx.x;
    if (c >= SD) return;
    const int r0 = blockIdx.y * RCH;
    const float* base = g_sim + ((size_t)n * LD + r0) * SD + c;
    float m = NEG_INF, s = 0.f;
    for (int r = 0; r < RCH; r++) {
        float v = base[(size_t)r * SD];
        if (v <= m) {
            s += expf(v - m);
        } else {
            s = s * expf(m - v) + 1.f;
            m = v;
        }
    }
    atomicCombineMS(&g_cms[n * SD + c], m, s);
}

// conf = exp(2*sim - rmax - cmax)/(rsum*csum); fused row-max and col-max of conf
__global__ void __launch_bounds__(256) k_conf(float* __restrict__ conf) {
    const int r0 = blockIdx.x * 32;             // 32 rows per block
    const int n  = r0 / LD;
    __shared__ float sred[8];
    float colmax[19];
    #pragma unroll
    for (int j = 0; j < 19; j++) colmax[j] = NEG_INF;

    for (int rr = 0; rr < 32; rr++) {
        const int row = r0 + rr;
        const float rm = g_rmax[row];
        const float inv_rs = 1.f / g_rsum[row];
        const float* sv = g_sim + (size_t)row * SD;
        float* cv = conf + (size_t)row * SD;
        float rcm = NEG_INF;
        #pragma unroll
        for (int j = 0; j < 19; j++) {
            int s = threadIdx.x + j * 256;
            if (s < SD) {
                unsigned long long ms = g_cms[n * SD + s];
                float cm = __uint_as_float((unsigned int)(ms & 0xffffffffu));
                float cs = __uint_as_float((unsigned int)(ms >> 32));
                float c = expf(2.f * sv[s] - rm - cm) * inv_rs * (1.f / cs);
                cv[s] = c;
                rcm = fmaxf(rcm, c);
                colmax[j] = fmaxf(colmax[j], c);
            }
        }
        float wm = warpMax(rcm);
        if ((threadIdx.x & 31) == 0) sred[threadIdx.x >> 5] = wm;
        __syncthreads();
        if (threadIdx.x == 0) {
            float bm = NEG_INF;
            #pragma unroll
            for (int i = 0; i < 8; i++) bm = fmaxf(bm, sred[i]);
            g_rcmax[row] = bm;
        }
        __syncthreads();
    }
    #pragma unroll
    for (int j = 0; j < 19; j++) {
        int s = threadIdx.x + j * 256;
        if (s < SD) atomicMaxFloat(&g_ccmax[n * SD + s], colmax[j]);
    }
}

// per-row match extraction (mutual NN + threshold + border); early-out for dead rows
__global__ void __launch_bounds__(256) k_match(const float* __restrict__ conf,
                                               float* __restrict__ mmask,
                                               float* __restrict__ jids,
                                               float* __restrict__ mconf,
                                               const int* __restrict__ h0p,
                                               const int* __restrict__ w0p,
                                               const int* __restrict__ h1p,
                                               const int* __restrict__ w1p) {
    const int row = blockIdx.x;
    const int n = row / LD;
    const int l = row % LD;
    const int w0c = *w0p;
    const int w1c = *w1p;
    (void)h0p; (void)h1p;   // L = h0c*w0c, S = h1c*w1c exactly; only first-BORDER rows/cols masked

    const bool v0 = ((l / w0c) >= BORDER) && ((l % w0c) >= BORDER);
    const float rm = g_rcmax[row];
    const float* crow = conf + (size_t)row * SD;

    int best = 0x7fffffff;
    if (v0 && rm > THRESH) {
        for (int s = threadIdx.x; s < SD; s += 256) {
            float c = crow[s];
            if (c > THRESH && c == rm && c == g_ccmax[n * SD + s]) {
                if (((s / w1c) >= BORDER) && ((s % w1c) >= BORDER)) best = min(best, s);
            }
        }
    }
    __shared__ int ired[8];
    int wmin = warpMinI(best);
    if ((threadIdx.x & 31) == 0) ired[threadIdx.x >> 5] = wmin;
    __syncthreads();
    if (threadIdx.x == 0) {
        int b = 0x7fffffff;
        #pragma unroll
        for (int i = 0; i < 8; i++) b = min(b, ired[i]);
        bool match = (b != 0x7fffffff);
        int j = match ? b : 0;              // argmax of all-False mask = 0
        mmask[row] = match ? 1.f : 0.f;
        jids[row]  = (float)j;
        mconf[row] = match ? crow[j] : 0.f;
    }
}

// ---------------- launch ----------------
extern "C" void kernel_launch(void* const* d_in, const int* in_sizes, int n_in,
                              void* d_out, int out_size) {
    const float* f0 = (const float*)d_in[0];
    const float* f1 = (const float*)d_in[1];
    const int* h0 = (const int*)d_in[2];
    const int* w0 = (const int*)d_in[3];
    const int* h1 = (const int*)d_in[4];
    const int* w1 = (const int*)d_in[5];

    float* out = (float*)d_out;
    float* conf = out;
    const size_t NLS = (size_t)NB * LD * SD;
    float* mm = out + NLS;
    float* jj = mm + NB * LD;
    float* mc = jj + NB * LD;

    k_init<<<(NB * SD + 255) / 256, 256>>>();
    dim3 gg((SD + BN - 1) / BN, (LD + BM - 1) / BM, NB);
    k_gemm<<<gg, 256>>>(f0, f1);
    k_rowstats<<<NB * LD, 256>>>();
    k_colstats<<<dim3((SD + 255) / 256, LD / RCH, NB), 256>>>();
    k_conf<<<NB * LD / 32, 256>>>(conf);
    k_match<<<NB * LD, 256>>>(conf, mm, jj, mc, h0, w0, h1, w1);
}

// round 3
// speedup vs baseline: 2.0072x; 2.0072x over previous
#include <cuda_runtime.h>
#include <cuda_bf16.h>
#include <cstdint>

#define NB 2
#define LD 4800
#define SD 4800
#define CD 256
#define TEMPER 0.1f
#define THRESH 0.2f
#define BORDER 2
#define NEG_INF __int_as_float(0xff800000)

#define KTOT 768          // A_cat=[hi|hi|lo], B_cat=[hi|lo|hi]
#define TM 128
#define TN 128
#define KC 64
#define NCHUNK (KTOT / KC)      // 12
#define ROWB 144                // 128B data + 16B pad per smem row (conflict-free LDSM)
#define ABUF_B (TM * ROWB)      // 18432
#define BBUF_B (TN * ROWB)      // 18432
#define STG_B (ABUF_B + BBUF_B) // 36864
#define DSMEM_B (2 * STG_B)     // 73728

// ---------------- scratch ----------------
__device__ float g_sim[(size_t)NB * LD * SD];
__device__ __align__(128) __nv_bfloat16 g_acat[(size_t)NB * LD * KTOT];
__device__ __align__(128) __nv_bfloat16 g_bcat[(size_t)NB * SD * KTOT];
__device__ float g_rmax[NB * LD];
__device__ float g_rsum[NB * LD];
__device__ unsigned long long g_cms[NB * SD];
__device__ float g_rcmax[NB * LD];
__device__ float g_ccmax[NB * SD];

// ---------------- PTX helpers (family-portable only) ----------------
__device__ __forceinline__ uint32_t s2u(const void* p) {
    uint32_t a;
    asm("{ .reg .u64 t; cvta.to.shared.u64 t, %1; cvt.u32.u64 %0, t; }" : "=r"(a) : "l"(p));
    return a;
}
__device__ __forceinline__ void ldsm_x4(uint32_t& r0, uint32_t& r1, uint32_t& r2, uint32_t& r3,
                                        uint32_t addr) {
    asm volatile("ldmatrix.sync.aligned.m8n8.x4.shared.b16 {%0,%1,%2,%3}, [%4];"
                 : "=r"(r0), "=r"(r1), "=r"(r2), "=r"(r3) : "r"(addr));
}
__device__ __forceinline__ void mma_bf16(float* d, const uint32_t* a, const uint32_t* b) {
    asm volatile(
        "mma.sync.aligned.m16n8k16.row.col.f32.bf16.bf16.f32 "
        "{%0,%1,%2,%3}, {%4,%5,%6,%7}, {%8,%9}, {%0,%1,%2,%3};"
        : "+f"(d[0]), "+f"(d[1]), "+f"(d[2]), "+f"(d[3])
        : "r"(a[0]), "r"(a[1]), "r"(a[2]), "r"(a[3]), "r"(b[0]), "r"(b[1]));
}
__device__ __forceinline__ void cp16(uint32_t dst, const void* src, bool pred) {
    int sz = pred ? 16 : 0;
    asm volatile("cp.async.cg.shared.global [%0], [%1], 16, %2;"
                 :: "r"(dst), "l"(src), "r"(sz) : "memory");
}
#define CP_COMMIT() asm volatile("cp.async.commit_group;" ::: "memory")
#define CP_WAIT1()  asm volatile("cp.async.wait_group 1;" ::: "memory")
#define CP_WAIT0()  asm volatile("cp.async.wait_group 0;" ::: "memory")

// ---------------- reduction helpers ----------------
__device__ __forceinline__ float warpMax(float v) {
    #pragma unroll
    for (int o = 16; o; o >>= 1) v = fmaxf(v, __shfl_xor_sync(0xffffffffu, v, o));
    return v;
}
__device__ __forceinline__ float warpSum(float v) {
    #pragma unroll
    for (int o = 16; o; o >>= 1) v += __shfl_xor_sync(0xffffffffu, v, o);
    return v;
}
__device__ __forceinline__ int warpMinI(int v) {
    #pragma unroll
    for (int o = 16; o; o >>= 1) v = min(v, __shfl_xor_sync(0xffffffffu, v, o));
    return v;
}
__device__ __forceinline__ void atomicMaxFloat(float* addr, float val) {
    unsigned int* ua = (unsigned int*)addr;
    unsigned int old = *ua;
    while (val > __uint_as_float(old)) {
        unsigned int assumed = old;
        old = atomicCAS(ua, assumed, __float_as_uint(val));
        if (old == assumed) break;
    }
}
__device__ __forceinline__ void atomicCombineMS(unsigned long long* addr, float m2, float s2) {
    unsigned long long old = *addr, assumed;
    do {
        assumed = old;
        float m1 = __uint_as_float((unsigned int)(assumed & 0xffffffffu));
        float s1 = __uint_as_float((unsigned int)(assumed >> 32));
        float nm = fmaxf(m1, m2);
        float ns = s1 * expf(m1 - nm) + s2 * expf(m2 - nm);
        unsigned long long nv =
            ((unsigned long long)__float_as_uint(ns) << 32) | __float_as_uint(nm);
        old = atomicCAS(addr, assumed, nv);
    } while (old != assumed);
}

// ---------------- kernels ----------------
__global__ void k_init() {
    int i = blockIdx.x * blockDim.x + threadIdx.x;
    if (i < NB * SD) {
        g_cms[i] = 0xff800000ull;
        g_ccmax[i] = NEG_INF;
    }
}

__global__ void __launch_bounds__(256) k_convert(const float* __restrict__ f0,
                                                 const float* __restrict__ f1) {
    size_t i = (size_t)blockIdx.x * blockDim.x + threadIdx.x;
    if (i >= (size_t)NB * LD * CD) return;
    size_t row = i / CD;
    int c = (int)(i % CD);
    {
        float x = f0[i];
        __nv_bfloat16 h = __float2bfloat16(x);
        __nv_bfloat16 l = __float2bfloat16(x - __bfloat162float(h));
        __nv_bfloat16* r = g_acat + row * KTOT;
        r[c] = h; r[CD + c] = h; r[2 * CD + c] = l;
    }
    {
        float x = f1[i];
        __nv_bfloat16 h = __float2bfloat16(x);
        __nv_bfloat16 l = __float2bfloat16(x - __bfloat162float(h));
        __nv_bfloat16* r = g_bcat + row * KTOT;
        r[c] = h; r[CD + c] = l; r[2 * CD + c] = h;
    }
}

// HMMA bf16 GEMM: sim[b, m, n] = (A_cat[m,:] . B_cat[n,:]) / (C*T)
__global__ void __launch_bounds__(256, 2) k_gemm_mma() {
    extern __shared__ char smem[];
    const int tid = threadIdx.x;
    const int wid = tid >> 5;
    const int lane = tid & 31;
    const int warp_m = wid & 1;   // 2 warps in M -> 64 rows each
    const int warp_n = wid >> 1;  // 4 warps in N -> 32 cols each

    const int b  = blockIdx.z;
    const int m0 = blockIdx.y * TM;
    const int n0 = blockIdx.x * TN;
    const int mrem = min(TM, LD - m0);
    const int nrem = min(TN, SD - n0);

    const __nv_bfloat16* Abase = g_acat + (size_t)(b * LD + m0) * KTOT;
    const __nv_bfloat16* Bbase = g_bcat + (size_t)(b * SD + n0) * KTOT;

    const uint32_t sbase = s2u(smem);

    float acc[4][4][4];
    #pragma unroll
    for (int i = 0; i < 4; i++)
        #pragma unroll
        for (int j = 0; j < 4; j++)
            #pragma unroll
            for (int q = 0; q < 4; q++) acc[i][j][q] = 0.f;

    // ---- async copy of one K-chunk into stage buf ----
    auto issue = [&](int chunk, int buf) {
        const int k0 = chunk * KC;
        const uint32_t sA = sbase + buf * STG_B;
        const uint32_t sB = sA + ABUF_B;
        #pragma unroll
        for (int i = 0; i < 4; i++) {
            int f = tid + i * 256;          // 0..1023
            int row = f >> 3, q = f & 7;
            bool pa = row < mrem;
            int ra = pa ? row : 0;
            cp16(sA + row * ROWB + q * 16,
                 Abase + (size_t)ra * KTOT + k0 + q * 8, pa);
            bool pb = row < nrem;
            int rb = pb ? row : 0;
            cp16(sB + row * ROWB + q * 16,
                 Bbase + (size_t)rb * KTOT + k0 + q * 8, pb);
        }
        CP_COMMIT();
    };

    issue(0, 0);
    issue(1, 1);

    const int g = lane >> 3;      // ldmatrix group 0..3
    const int lr = lane & 7;

    for (int s = 0; s < NCHUNK; s++) {
        if (s == NCHUNK - 1) { CP_WAIT0(); } else { CP_WAIT1(); }
        __syncthreads();
        const int buf = s & 1;
        const uint32_t sA = sbase + buf * STG_B;
        const uint32_t sB = sA + ABUF_B;

        #pragma unroll
        for (int ks = 0; ks < KC / 16; ks++) {
            const int kb = ks * 16;
            uint32_t a[4][4];
            #pragma unroll
            for (int mi = 0; mi < 4; mi++) {
                uint32_t addr = sA + (uint32_t)((warp_m * 64 + mi * 16 + (g & 1) * 8 + lr) * ROWB
                                                + (kb + (g >> 1) * 8) * 2);
                ldsm_x4(a[mi][0], a[mi][1], a[mi][2], a[mi][3], addr);
            }
            uint32_t bfr[4][2];
            #pragma unroll
            for (int p = 0; p < 2; p++) {
                uint32_t r0, r1, r2, r3;
                uint32_t addr = sB + (uint32_t)((warp_n * 32 + p * 16 + (g >> 1) * 8 + lr) * ROWB
                                                + (kb + (g & 1) * 8) * 2);
                ldsm_x4(r0, r1, r2, r3, addr);
                bfr[p * 2 + 0][0] = r0; bfr[p * 2 + 0][1] = r1;
                bfr[p * 2 + 1][0] = r2; bfr[p * 2 + 1][1] = r3;
            }
            #pragma unroll
            for (int mi = 0; mi < 4; mi++)
                #pragma unroll
                for (int ni = 0; ni < 4; ni++)
                    mma_bf16(acc[mi][ni], a[mi], bfr[ni]);
        }
        __syncthreads();
        if (s + 2 < NCHUNK) issue(s + 2, buf);
    }

    // ---- epilogue ----
    const float sc = 1.0f / ((float)CD * TEMPER);
    const int qrow = lane >> 2;         // 0..7
    const int qcol = (lane & 3) * 2;    // 0,2,4,6
    #pragma unroll
    for (int mi = 0; mi < 4; mi++) {
        #pragma unroll
        for (int half = 0; half < 2; half++) {
            int lrow = warp_m * 64 + mi * 16 + half * 8 + qrow;
            if (lrow >= mrem) continue;
            float* dst = g_sim + ((size_t)(b * LD) + m0 + lrow) * SD + n0;
            #pragma unroll
            for (int ni = 0; ni < 4; ni++) {
                int lcol = warp_n * 32 + ni * 8 + qcol;
                if (lcol < nrem) {
                    float2 o;
                    o.x = acc[mi][ni][half * 2 + 0] * sc;
                    o.y = acc[mi][ni][half * 2 + 1] * sc;
                    *reinterpret_cast<float2*>(dst + lcol) = o;
                }
            }
        }
    }
}

// per-row max + sumexp
__global__ void __launch_bounds__(256) k_rowstats() {
    const int row = blockIdx.x;
    const float* r = g_sim + (size_t)row * SD;
    float v[19];
    float m = NEG_INF;
    #pragma unroll
    for (int j = 0; j < 19; j++) {
        int s = threadIdx.x + j * 256;
        v[j] = (s < SD) ? r[s] : NEG_INF;
        m = fmaxf(m, v[j]);
    }
    __shared__ float sred[8];
    float wm = warpMax(m);
    if ((threadIdx.x & 31) == 0) sred[threadIdx.x >> 5] = wm;
    __syncthreads();
    float bm = NEG_INF;
    #pragma unroll
    for (int i = 0; i < 8; i++) bm = fmaxf(bm, sred[i]);
    __syncthreads();
    float sum = 0.f;
    #pragma unroll
    for (int j = 0; j < 19; j++) sum += expf(v[j] - bm);
    float ws = warpSum(sum);
    if ((threadIdx.x & 31) == 0) sred[threadIdx.x >> 5] = ws;
    __syncthreads();
    if (threadIdx.x == 0) {
        float t = 0.f;
        #pragma unroll
        for (int i = 0; i < 8; i++) t += sred[i];
        g_rmax[row] = bm;
        g_rsum[row] = t;
    }
}

// column stats, 150-row stripes
#define RCH 150
__global__ void __launch_bounds__(256) k_colstats() {
    const int n = blockIdx.z;
    const int c = blockIdx.x * 256 + threadIdx.x;
    if (c >= SD) return;
    const int r0 = blockIdx.y * RCH;
    const float* base = g_sim + ((size_t)n * LD + r0) * SD + c;
    float m = NEG_INF, s = 0.f;
    for (int r = 0; r < RCH; r++) {
        float v = base[(size_t)r * SD];
        if (v <= m) s += expf(v - m);
        else { s = s * expf(m - v) + 1.f; m = v; }
    }
    atomicCombineMS(&g_cms[n * SD + c], m, s);
}

// conf + fused row/col conf maxes
#define CROWS 8
__global__ void __launch_bounds__(256) k_conf(float* __restrict__ conf) {
    const int r0 = blockIdx.x * CROWS;
    const int n = r0 / LD;
    __shared__ float sred[8];
    float colmax[19];
    #pragma unroll
    for (int j = 0; j < 19; j++) colmax[j] = NEG_INF;

    for (int rr = 0; rr < CROWS; rr++) {
        const int row = r0 + rr;
        const float rm = g_rmax[row];
        const float inv_rs = 1.f / g_rsum[row];
        const float* sv = g_sim + (size_t)row * SD;
        float* cv = conf + (size_t)row * SD;
        float rcm = NEG_INF;
        #pragma unroll
        for (int j = 0; j < 19; j++) {
            int s = threadIdx.x + j * 256;
            if (s < SD) {
                unsigned long long ms = g_cms[n * SD + s];
                float cm = __uint_as_float((unsigned int)(ms & 0xffffffffu));
                float cs = __uint_as_float((unsigned int)(ms >> 32));
                float c = expf(2.f * sv[s] - rm - cm) * inv_rs * (1.f / cs);
                cv[s] = c;
                rcm = fmaxf(rcm, c);
                colmax[j] = fmaxf(colmax[j], c);
            }
        }
        float wm = warpMax(rcm);
        if ((threadIdx.x & 31) == 0) sred[threadIdx.x >> 5] = wm;
        __syncthreads();
        if (threadIdx.x == 0) {
            float bm = NEG_INF;
            #pragma unroll
            for (int i = 0; i < 8; i++) bm = fmaxf(bm, sred[i]);
            g_rcmax[row] = bm;
        }
        __syncthreads();
    }
    #pragma unroll
    for (int j = 0; j < 19; j++) {
        int s = threadIdx.x + j * 256;
        if (s < SD) atomicMaxFloat(&g_ccmax[n * SD + s], colmax[j]);
    }
}

// match extraction
__global__ void __launch_bounds__(256) k_match(const float* __restrict__ conf,
                                               float* __restrict__ mmask,
                                               float* __restrict__ jids,
                                               float* __restrict__ mconf,
                                               const int* __restrict__ w0p,
                                               const int* __restrict__ w1p) {
    const int row = blockIdx.x;
    const int n = row / LD;
    const int l = row % LD;
    const int w0c = *w0p;
    const int w1c = *w1p;

    const bool v0 = ((l / w0c) >= BORDER) && ((l % w0c) >= BORDER);
    const float rm = g_rcmax[row];
    const float* crow = conf + (size_t)row * SD;

    int best = 0x7fffffff;
    if (v0 && rm > THRESH) {
        for (int s = threadIdx.x; s < SD; s += 256) {
            float c = crow[s];
            if (c > THRESH && c == rm && c == g_ccmax[n * SD + s]) {
                if (((s / w1c) >= BORDER) && ((s % w1c) >= BORDER)) best = min(best, s);
            }
        }
    }
    __shared__ int ired[8];
    int wmin = warpMinI(best);
    if ((threadIdx.x & 31) == 0) ired[threadIdx.x >> 5] = wmin;
    __syncthreads();
    if (threadIdx.x == 0) {
        int bmin = 0x7fffffff;
        #pragma unroll
        for (int i = 0; i < 8; i++) bmin = min(bmin, ired[i]);
        bool match = (bmin != 0x7fffffff);
        int j = match ? bmin : 0;
        mmask[row] = match ? 1.f : 0.f;
        jids[row]  = (float)j;
        mconf[row] = match ? crow[j] : 0.f;
    }
}

// ---------------- launch ----------------
extern "C" void kernel_launch(void* const* d_in, const int* in_sizes, int n_in,
                              void* d_out, int out_size) {
    const float* f0 = (const float*)d_in[0];
    const float* f1 = (const float*)d_in[1];
    const int* w0 = (const int*)d_in[3];
    const int* w1 = (const int*)d_in[5];

    float* out = (float*)d_out;
    float* conf = out;
    const size_t NLS = (size_t)NB * LD * SD;
    float* mm = out + NLS;
    float* jj = mm + NB * LD;
    float* mc = jj + NB * LD;

    static int cfg_done = 0;
    if (!cfg_done) {
        cudaFuncSetAttribute(k_gemm_mma, cudaFuncAttributeMaxDynamicSharedMemorySize, DSMEM_B);
        cfg_done = 1;
    }

    k_init<<<(NB * SD + 255) / 256, 256>>>();
    k_convert<<<(NB * LD * CD + 255) / 256, 256>>>(f0, f1);
    dim3 gg((SD + TN - 1) / TN, (LD + TM - 1) / TM, NB);
    k_gemm_mma<<<gg, 256, DSMEM_B>>>();
    k_rowstats<<<NB * LD, 256>>>();
    k_colstats<<<dim3((SD + 255) / 256, LD / RCH, NB), 256>>>();
    k_conf<<<NB * LD / CROWS, 256>>>(conf);
    k_match<<<NB * LD, 256>>>(conf, mm, jj, mc, w0, w1);
}

// round 4
// speedup vs baseline: 2.3030x; 1.1473x over previous
#include <cuda_runtime.h>
#include <cuda_bf16.h>
#include <cstdint>

#define NB 2
#define LD 4800
#define SD 4800
#define CD 256
#define TEMPER 0.1f
#define THRESH 0.2f
#define BORDER 2
#define NEG_INF __int_as_float(0xff800000)

#define KTOT 768          // A_cat=[hi|hi|lo], B_cat=[hi|lo|hi]
#define TM 128
#define TN 128
#define KC 64
#define NCHUNK (KTOT / KC)      // 12
#define ROWB 144                // 128B data + 16B pad per smem row
#define ABUF_B (TM * ROWB)
#define BBUF_B (TN * ROWB)
#define STG_B (ABUF_B + BBUF_B) // 36864
#define NSTG 3
#define DSMEM_B (NSTG * STG_B)  // 110592

// ---------------- scratch ----------------
__device__ float g_sim[(size_t)NB * LD * SD];
__device__ __align__(128) __nv_bfloat16 g_acat[(size_t)NB * LD * KTOT];
__device__ __align__(128) __nv_bfloat16 g_bcat[(size_t)NB * SD * KTOT];
__device__ float g_rsum[NB * LD];     // sum of exp(sim) per row
__device__ float g_csum[NB * SD];     // sum of exp(sim) per col
__device__ float g_rcmax[NB * LD];    // row max of conf
__device__ float g_ccmax[NB * SD];    // col max of conf

// ---------------- PTX helpers (family-portable) ----------------
__device__ __forceinline__ uint32_t s2u(const void* p) {
    uint32_t a;
    asm("{ .reg .u64 t; cvta.to.shared.u64 t, %1; cvt.u32.u64 %0, t; }" : "=r"(a) : "l"(p));
    return a;
}
__device__ __forceinline__ void ldsm_x4(uint32_t& r0, uint32_t& r1, uint32_t& r2, uint32_t& r3,
                                        uint32_t addr) {
    asm volatile("ldmatrix.sync.aligned.m8n8.x4.shared.b16 {%0,%1,%2,%3}, [%4];"
                 : "=r"(r0), "=r"(r1), "=r"(r2), "=r"(r3) : "r"(addr));
}
__device__ __forceinline__ void mma_bf16(float* d, const uint32_t* a, const uint32_t* b) {
    asm volatile(
        "mma.sync.aligned.m16n8k16.row.col.f32.bf16.bf16.f32 "
        "{%0,%1,%2,%3}, {%4,%5,%6,%7}, {%8,%9}, {%0,%1,%2,%3};"
        : "+f"(d[0]), "+f"(d[1]), "+f"(d[2]), "+f"(d[3])
        : "r"(a[0]), "r"(a[1]), "r"(a[2]), "r"(a[3]), "r"(b[0]), "r"(b[1]));
}
__device__ __forceinline__ void cp16(uint32_t dst, const void* src, bool pred) {
    int sz = pred ? 16 : 0;
    asm volatile("cp.async.cg.shared.global [%0], [%1], 16, %2;"
                 :: "r"(dst), "l"(src), "r"(sz) : "memory");
}
#define CP_COMMIT() asm volatile("cp.async.commit_group;" ::: "memory")
#define CP_WAIT1()  asm volatile("cp.async.wait_group 1;" ::: "memory")
#define CP_WAIT0()  asm volatile("cp.async.wait_group 0;" ::: "memory")

// ---------------- reduction helpers ----------------
__device__ __forceinline__ float warpMax(float v) {
    #pragma unroll
    for (int o = 16; o; o >>= 1) v = fmaxf(v, __shfl_xor_sync(0xffffffffu, v, o));
    return v;
}
__device__ __forceinline__ int warpMinI(int v) {
    #pragma unroll
    for (int o = 16; o; o >>= 1) v = min(v, __shfl_xor_sync(0xffffffffu, v, o));
    return v;
}
__device__ __forceinline__ void atomicMaxFloat(float* addr, float val) {
    unsigned int* ua = (unsigned int*)addr;
    unsigned int old = *ua;
    while (val > __uint_as_float(old)) {
        unsigned int assumed = old;
        old = atomicCAS(ua, assumed, __float_as_uint(val));
        if (old == assumed) break;
    }
}

// ---------------- kernels ----------------
__global__ void k_init() {
    int i = blockIdx.x * blockDim.x + threadIdx.x;
    if (i < NB * SD) {
        g_rsum[i] = 0.f;
        g_csum[i] = 0.f;
        g_ccmax[i] = NEG_INF;
    }
}

__global__ void __launch_bounds__(256) k_convert(const float* __restrict__ f0,
                                                 const float* __restrict__ f1) {
    size_t i = (size_t)blockIdx.x * blockDim.x + threadIdx.x;
    if (i >= (size_t)NB * LD * CD) return;
    size_t row = i / CD;
    int c = (int)(i % CD);
    {
        float x = f0[i];
        __nv_bfloat16 h = __float2bfloat16(x);
        __nv_bfloat16 l = __float2bfloat16(x - __bfloat162float(h));
        __nv_bfloat16* r = g_acat + row * KTOT;
        r[c] = h; r[CD + c] = h; r[2 * CD + c] = l;
    }
    {
        float x = f1[i];
        __nv_bfloat16 h = __float2bfloat16(x);
        __nv_bfloat16 l = __float2bfloat16(x - __bfloat162float(h));
        __nv_bfloat16* r = g_bcat + row * KTOT;
        r[c] = h; r[CD + c] = l; r[2 * CD + c] = h;
    }
}

// HMMA bf16 GEMM + fused exp-sum stats in epilogue
__global__ void __launch_bounds__(256, 2) k_gemm_mma() {
    extern __shared__ char smem[];
    const int tid = threadIdx.x;
    const int wid = tid >> 5;
    const int lane = tid & 31;
    const int warp_m = wid & 1;
    const int warp_n = wid >> 1;

    const int b  = blockIdx.z;
    const int m0 = blockIdx.y * TM;
    const int n0 = blockIdx.x * TN;
    const int mrem = min(TM, LD - m0);
    const int nrem = min(TN, SD - n0);

    const __nv_bfloat16* Abase = g_acat + (size_t)(b * LD + m0) * KTOT;
    const __nv_bfloat16* Bbase = g_bcat + (size_t)(b * SD + n0) * KTOT;
    const uint32_t sbase = s2u(smem);

    float acc[4][4][4];
    #pragma unroll
    for (int i = 0; i < 4; i++)
        #pragma unroll
        for (int j = 0; j < 4; j++)
            #pragma unroll
            for (int q = 0; q < 4; q++) acc[i][j][q] = 0.f;

    auto issue = [&](int chunk, int buf) {
        const int k0 = chunk * KC;
        const uint32_t sA = sbase + buf * STG_B;
        const uint32_t sB = sA + ABUF_B;
        #pragma unroll
        for (int i = 0; i < 4; i++) {
            int f = tid + i * 256;
            int row = f >> 3, q = f & 7;
            bool pa = row < mrem;
            int ra = pa ? row : 0;
            cp16(sA + row * ROWB + q * 16, Abase + (size_t)ra * KTOT + k0 + q * 8, pa);
            bool pb = row < nrem;
            int rb = pb ? row : 0;
            cp16(sB + row * ROWB + q * 16, Bbase + (size_t)rb * KTOT + k0 + q * 8, pb);
        }
        CP_COMMIT();
    };

    issue(0, 0);
    issue(1, 1);

    const int g = lane >> 3;
    const int lr = lane & 7;

    for (int s = 0; s < NCHUNK; s++) {
        if (s == NCHUNK - 1) { CP_WAIT0(); } else { CP_WAIT1(); }
        __syncthreads();
        const int buf = s % NSTG;
        const uint32_t sA = sbase + buf * STG_B;
        const uint32_t sB = sA + ABUF_B;
        if (s + 2 < NCHUNK) issue(s + 2, (s + 2) % NSTG);

        #pragma unroll
        for (int ks = 0; ks < KC / 16; ks++) {
            const int kb = ks * 16;
            uint32_t a[4][4];
            #pragma unroll
            for (int mi = 0; mi < 4; mi++) {
                uint32_t addr = sA + (uint32_t)((warp_m * 64 + mi * 16 + (g & 1) * 8 + lr) * ROWB
                                                + (kb + (g >> 1) * 8) * 2);
                ldsm_x4(a[mi][0], a[mi][1], a[mi][2], a[mi][3], addr);
            }
            uint32_t bfr[4][2];
            #pragma unroll
            for (int p = 0; p < 2; p++) {
                uint32_t r0, r1, r2, r3;
                uint32_t addr = sB + (uint32_t)((warp_n * 32 + p * 16 + (g >> 1) * 8 + lr) * ROWB
                                                + (kb + (g & 1) * 8) * 2);
                ldsm_x4(r0, r1, r2, r3, addr);
                bfr[p * 2 + 0][0] = r0; bfr[p * 2 + 0][1] = r1;
                bfr[p * 2 + 1][0] = r2; bfr[p * 2 + 1][1] = r3;
            }
            #pragma unroll
            for (int mi = 0; mi < 4; mi++)
                #pragma unroll
                for (int ni = 0; ni < 4; ni++)
                    mma_bf16(acc[mi][ni], a[mi], bfr[ni]);
        }
        __syncthreads();
    }

    // ---- epilogue: store sim + fused exp-sum row/col stats ----
    const float sc = 1.0f / ((float)CD * TEMPER);
    const int qrow = lane >> 2;
    const int qcol = (lane & 3) * 2;

    float rowsum[4][2];
    float colsum[4][2];
    #pragma unroll
    for (int i = 0; i < 4; i++) { rowsum[i][0] = rowsum[i][1] = 0.f; colsum[i][0] = colsum[i][1] = 0.f; }

    #pragma unroll
    for (int mi = 0; mi < 4; mi++) {
        #pragma unroll
        for (int half = 0; half < 2; half++) {
            int lrow = warp_m * 64 + mi * 16 + half * 8 + qrow;
            bool rv = lrow < mrem;
            float* dst = g_sim + ((size_t)(b * LD) + m0 + lrow) * SD + n0;
            #pragma unroll
            for (int ni = 0; ni < 4; ni++) {
                int lcol = warp_n * 32 + ni * 8 + qcol;
                bool cv = lcol < nrem;             // nrem even -> pair valid together
                float vx = acc[mi][ni][half * 2 + 0] * sc;
                float vy = acc[mi][ni][half * 2 + 1] * sc;
                if (rv && cv) {
                    float2 o; o.x = vx; o.y = vy;
                    *reinterpret_cast<float2*>(dst + lcol) = o;
                }
                float ex = (rv && cv) ? expf(vx) : 0.f;
                float ey = (rv && cv) ? expf(vy) : 0.f;
                rowsum[mi][half] += ex + ey;
                colsum[ni][0] += ex;
                colsum[ni][1] += ey;
            }
        }
    }
    // row reduction within quad (cols live in lane&3)
    #pragma unroll
    for (int mi = 0; mi < 4; mi++) {
        #pragma unroll
        for (int half = 0; half < 2; half++) {
            float r = rowsum[mi][half];
            r += __shfl_xor_sync(0xffffffffu, r, 1);
            r += __shfl_xor_sync(0xffffffffu, r, 2);
            if ((lane & 3) == 0) {
                int lrow = warp_m * 64 + mi * 16 + half * 8 + qrow;
                if (lrow < mrem) atomicAdd(&g_rsum[b * LD + m0 + lrow], r);
            }
        }
    }
    // col reduction across quads (rows live in lane>>2)
    #pragma unroll
    for (int ni = 0; ni < 4; ni++) {
        #pragma unroll
        for (int c = 0; c < 2; c++) {
            float v = colsum[ni][c];
            v += __shfl_xor_sync(0xffffffffu, v, 4);
            v += __shfl_xor_sync(0xffffffffu, v, 8);
            v += __shfl_xor_sync(0xffffffffu, v, 16);
            if (lane < 4) {
                int lcol = warp_n * 32 + ni * 8 + qcol + c;
                if (lcol < nrem) atomicAdd(&g_csum[b * SD + n0 + lcol], v);
            }
        }
    }
}

// conf = exp(2*sim)/(rsum*csum); fused row/col conf maxes
#define CROWS 8
__global__ void __launch_bounds__(256) k_conf(float* __restrict__ conf) {
    const int r0 = blockIdx.x * CROWS;
    const int n = r0 / LD;
    __shared__ float sred[8];

    float cinv[19];
    #pragma unroll
    for (int j = 0; j < 19; j++) {
        int s = threadIdx.x + j * 256;
        cinv[j] = (s < SD) ? (1.f / g_csum[n * SD + s]) : 0.f;
    }
    float colmax[19];
    #pragma unroll
    for (int j = 0; j < 19; j++) colmax[j] = NEG_INF;

    for (int rr = 0; rr < CROWS; rr++) {
        const int row = r0 + rr;
        const float inv_rs = 1.f / g_rsum[row];
        const float* sv = g_sim + (size_t)row * SD;
        float* cv = conf + (size_t)row * SD;
        float rcm = NEG_INF;
        #pragma unroll
        for (int j = 0; j < 19; j++) {
            int s = threadIdx.x + j * 256;
            if (s < SD) {
                float c = expf(2.f * sv[s]) * inv_rs * cinv[j];
                cv[s] = c;
                rcm = fmaxf(rcm, c);
                colmax[j] = fmaxf(colmax[j], c);
            }
        }
        float wm = warpMax(rcm);
        if ((threadIdx.x & 31) == 0) sred[threadIdx.x >> 5] = wm;
        __syncthreads();
        if (threadIdx.x == 0) {
            float bm = NEG_INF;
            #pragma unroll
            for (int i = 0; i < 8; i++) bm = fmaxf(bm, sred[i]);
            g_rcmax[row] = bm;
        }
        __syncthreads();
    }
    #pragma unroll
    for (int j = 0; j < 19; j++) {
        int s = threadIdx.x + j * 256;
        if (s < SD) atomicMaxFloat(&g_ccmax[n * SD + s], colmax[j]);
    }
}

// match extraction
__global__ void __launch_bounds__(256) k_match(const float* __restrict__ conf,
                                               float* __restrict__ mmask,
                                               float* __restrict__ jids,
                                               float* __restrict__ mconf,
                                               const int* __restrict__ w0p,
                                               const int* __restrict__ w1p) {
    const int row = blockIdx.x;
    const int n = row / LD;
    const int l = row % LD;
    const int w0c = *w0p;
    const int w1c = *w1p;

    const bool v0 = ((l / w0c) >= BORDER) && ((l % w0c) >= BORDER);
    const float rm = g_rcmax[row];
    const float* crow = conf + (size_t)row * SD;

    int best = 0x7fffffff;
    if (v0 && rm > THRESH) {
        for (int s = threadIdx.x; s < SD; s += 256) {
            float c = crow[s];
            if (c > THRESH && c == rm && c == g_ccmax[n * SD + s]) {
                if (((s / w1c) >= BORDER) && ((s % w1c) >= BORDER)) best = min(best, s);
            }
        }
    }
    __shared__ int ired[8];
    int wmin = warpMinI(best);
    if ((threadIdx.x & 31) == 0) ired[threadIdx.x >> 5] = wmin;
    __syncthreads();
    if (threadIdx.x == 0) {
        int bmin = 0x7fffffff;
        #pragma unroll
        for (int i = 0; i < 8; i++) bmin = min(bmin, ired[i]);
        bool match = (bmin != 0x7fffffff);
        int j = match ? bmin : 0;
        mmask[row] = match ? 1.f : 0.f;
        jids[row]  = (float)j;
        mconf[row] = match ? crow[j] : 0.f;
    }
}

// ---------------- launch ----------------
extern "C" void kernel_launch(void* const* d_in, const int* in_sizes, int n_in,
                              void* d_out, int out_size) {
    const float* f0 = (const float*)d_in[0];
    const float* f1 = (const float*)d_in[1];
    const int* w0 = (const int*)d_in[3];
    const int* w1 = (const int*)d_in[5];

    float* out = (float*)d_out;
    float* conf = out;
    const size_t NLS = (size_t)NB * LD * SD;
    float* mm = out + NLS;
    float* jj = mm + NB * LD;
    float* mc = jj + NB * LD;

    static int cfg_done = 0;
    if (!cfg_done) {
        cudaFuncSetAttribute(k_gemm_mma, cudaFuncAttributeMaxDynamicSharedMemorySize, DSMEM_B);
        cfg_done = 1;
    }

    k_init<<<(NB * SD + 255) / 256, 256>>>();
    k_convert<<<(NB * LD * CD + 255) / 256, 256>>>(f0, f1);
    dim3 gg((SD + TN - 1) / TN, (LD + TM - 1) / TM, NB);
    k_gemm_mma<<<gg, 256, DSMEM_B>>>();
    k_conf<<<NB * LD / CROWS, 256>>>(conf);
    k_match<<<NB * LD, 256>>>(conf, mm, jj, mc, w0, w1);
}

// round 5
// speedup vs baseline: 3.0802x; 1.3375x over previous
#include <cuda_runtime.h>
#include <cuda_bf16.h>
#include <cstdint>

#define NB 2
#define LD 4800
#define SD 4800
#define CD 256
#define TEMPER 0.1f
#define THRESH 0.2f
#define BORDER 2

#define KTOT 768          // A_cat=[hi|hi|lo], B_cat=[hi|lo|hi]
#define TM 128
#define TN 128
#define KC 64
#define NCHUNK (KTOT / KC)
#define ROWB 144
#define ABUF_B (TM * ROWB)
#define BBUF_B (TN * ROWB)
#define STG_B (ABUF_B + BBUF_B)
#define NSTG 3
#define DSMEM_B (NSTG * STG_B)

// ---------------- scratch ----------------
__device__ float g_sim[(size_t)NB * LD * SD];
__device__ __align__(128) __nv_bfloat16 g_acat[(size_t)NB * LD * KTOT];
__device__ __align__(128) __nv_bfloat16 g_bcat[(size_t)NB * SD * KTOT];
__device__ float g_rsum[NB * LD];
__device__ float g_csum[NB * SD];
__device__ int g_rcmax[NB * LD];      // conf row max (positive-float bits as int)
__device__ int g_ccmax[NB * SD];      // conf col max (positive-float bits as int)

// ---------------- PTX helpers ----------------
__device__ __forceinline__ uint32_t s2u(const void* p) {
    uint32_t a;
    asm("{ .reg .u64 t; cvta.to.shared.u64 t, %1; cvt.u32.u64 %0, t; }" : "=r"(a) : "l"(p));
    return a;
}
__device__ __forceinline__ void ldsm_x4(uint32_t& r0, uint32_t& r1, uint32_t& r2, uint32_t& r3,
                                        uint32_t addr) {
    asm volatile("ldmatrix.sync.aligned.m8n8.x4.shared.b16 {%0,%1,%2,%3}, [%4];"
                 : "=r"(r0), "=r"(r1), "=r"(r2), "=r"(r3) : "r"(addr));
}
__device__ __forceinline__ void mma_bf16(float* d, const uint32_t* a, const uint32_t* b) {
    asm volatile(
        "mma.sync.aligned.m16n8k16.row.col.f32.bf16.bf16.f32 "
        "{%0,%1,%2,%3}, {%4,%5,%6,%7}, {%8,%9}, {%0,%1,%2,%3};"
        : "+f"(d[0]), "+f"(d[1]), "+f"(d[2]), "+f"(d[3])
        : "r"(a[0]), "r"(a[1]), "r"(a[2]), "r"(a[3]), "r"(b[0]), "r"(b[1]));
}
__device__ __forceinline__ void cp16(uint32_t dst, const void* src, bool pred) {
    int sz = pred ? 16 : 0;
    asm volatile("cp.async.cg.shared.global [%0], [%1], 16, %2;"
                 :: "r"(dst), "l"(src), "r"(sz) : "memory");
}
#define CP_COMMIT() asm volatile("cp.async.commit_group;" ::: "memory")
#define CP_WAIT1()  asm volatile("cp.async.wait_group 1;" ::: "memory")
#define CP_WAIT0()  asm volatile("cp.async.wait_group 0;" ::: "memory")

__device__ __forceinline__ float warpMaxF(float v) {
    #pragma unroll
    for (int o = 16; o; o >>= 1) v = fmaxf(v, __shfl_xor_sync(0xffffffffu, v, o));
    return v;
}
__device__ __forceinline__ int warpMinI(int v) {
    #pragma unroll
    for (int o = 16; o; o >>= 1) v = min(v, __shfl_xor_sync(0xffffffffu, v, o));
    return v;
}

// ---------------- kernels ----------------
__global__ void k_init() {
    int i = blockIdx.x * blockDim.x + threadIdx.x;
    if (i < NB * SD) {
        g_rsum[i] = 0.f;
        g_csum[i] = 0.f;
        g_rcmax[i] = 0;
        g_ccmax[i] = 0;
    }
}

__global__ void __launch_bounds__(256) k_convert(const float* __restrict__ f0,
                                                 const float* __restrict__ f1) {
    size_t i = (size_t)blockIdx.x * blockDim.x + threadIdx.x;
    if (i >= (size_t)NB * LD * CD) return;
    size_t row = i / CD;
    int c = (int)(i % CD);
    {
        float x = f0[i];
        __nv_bfloat16 h = __float2bfloat16(x);
        __nv_bfloat16 l = __float2bfloat16(x - __bfloat162float(h));
        __nv_bfloat16* r = g_acat + row * KTOT;
        r[c] = h; r[CD + c] = h; r[2 * CD + c] = l;
    }
    {
        float x = f1[i];
        __nv_bfloat16 h = __float2bfloat16(x);
        __nv_bfloat16 l = __float2bfloat16(x - __bfloat162float(h));
        __nv_bfloat16* r = g_bcat + row * KTOT;
        r[c] = h; r[CD + c] = l; r[2 * CD + c] = h;
    }
}

// HMMA bf16 GEMM + fused exp-sum stats
__global__ void __launch_bounds__(256, 2) k_gemm_mma() {
    extern __shared__ char smem[];
    const int tid = threadIdx.x;
    const int wid = tid >> 5;
    const int lane = tid & 31;
    const int warp_m = wid & 1;
    const int warp_n = wid >> 1;

    const int b  = blockIdx.z;
    const int m0 = blockIdx.y * TM;
    const int n0 = blockIdx.x * TN;
    const int mrem = min(TM, LD - m0);
    const int nrem = min(TN, SD - n0);

    const __nv_bfloat16* Abase = g_acat + (size_t)(b * LD + m0) * KTOT;
    const __nv_bfloat16* Bbase = g_bcat + (size_t)(b * SD + n0) * KTOT;
    const uint32_t sbase = s2u(smem);

    float acc[4][4][4];
    #pragma unroll
    for (int i = 0; i < 4; i++)
        #pragma unroll
        for (int j = 0; j < 4; j++)
            #pragma unroll
            for (int q = 0; q < 4; q++) acc[i][j][q] = 0.f;

    auto issue = [&](int chunk, int buf) {
        const int k0 = chunk * KC;
        const uint32_t sA = sbase + buf * STG_B;
        const uint32_t sB = sA + ABUF_B;
        #pragma unroll
        for (int i = 0; i < 4; i++) {
            int f = tid + i * 256;
            int row = f >> 3, q = f & 7;
            bool pa = row < mrem;
            int ra = pa ? row : 0;
            cp16(sA + row * ROWB + q * 16, Abase + (size_t)ra * KTOT + k0 + q * 8, pa);
            bool pb = row < nrem;
            int rb = pb ? row : 0;
            cp16(sB + row * ROWB + q * 16, Bbase + (size_t)rb * KTOT + k0 + q * 8, pb);
        }
        CP_COMMIT();
    };

    issue(0, 0);
    issue(1, 1);

    const int g = lane >> 3;
    const int lr = lane & 7;

    for (int s = 0; s < NCHUNK; s++) {
        if (s == NCHUNK - 1) { CP_WAIT0(); } else { CP_WAIT1(); }
        __syncthreads();
        const int buf = s % NSTG;
        const uint32_t sA = sbase + buf * STG_B;
        const uint32_t sB = sA + ABUF_B;
        if (s + 2 < NCHUNK) issue(s + 2, (s + 2) % NSTG);

        #pragma unroll
        for (int ks = 0; ks < KC / 16; ks++) {
            const int kb = ks * 16;
            uint32_t a[4][4];
            #pragma unroll
            for (int mi = 0; mi < 4; mi++) {
                uint32_t addr = sA + (uint32_t)((warp_m * 64 + mi * 16 + (g & 1) * 8 + lr) * ROWB
                                                + (kb + (g >> 1) * 8) * 2);
                ldsm_x4(a[mi][0], a[mi][1], a[mi][2], a[mi][3], addr);
            }
            uint32_t bfr[4][2];
            #pragma unroll
            for (int p = 0; p < 2; p++) {
                uint32_t r0, r1, r2, r3;
                uint32_t addr = sB + (uint32_t)((warp_n * 32 + p * 16 + (g >> 1) * 8 + lr) * ROWB
                                                + (kb + (g & 1) * 8) * 2);
                ldsm_x4(r0, r1, r2, r3, addr);
                bfr[p * 2 + 0][0] = r0; bfr[p * 2 + 0][1] = r1;
                bfr[p * 2 + 1][0] = r2; bfr[p * 2 + 1][1] = r3;
            }
            #pragma unroll
            for (int mi = 0; mi < 4; mi++)
                #pragma unroll
                for (int ni = 0; ni < 4; ni++)
                    mma_bf16(acc[mi][ni], a[mi], bfr[ni]);
        }
        __syncthreads();
    }

    const float sc = 1.0f / ((float)CD * TEMPER);
    const int qrow = lane >> 2;
    const int qcol = (lane & 3) * 2;

    float rowsum[4][2];
    float colsum[4][2];
    #pragma unroll
    for (int i = 0; i < 4; i++) { rowsum[i][0] = rowsum[i][1] = 0.f; colsum[i][0] = colsum[i][1] = 0.f; }

    #pragma unroll
    for (int mi = 0; mi < 4; mi++) {
        #pragma unroll
        for (int half = 0; half < 2; half++) {
            int lrow = warp_m * 64 + mi * 16 + half * 8 + qrow;
            bool rv = lrow < mrem;
            float* dst = g_sim + ((size_t)(b * LD) + m0 + lrow) * SD + n0;
            #pragma unroll
            for (int ni = 0; ni < 4; ni++) {
                int lcol = warp_n * 32 + ni * 8 + qcol;
                bool cv = lcol < nrem;
                float vx = acc[mi][ni][half * 2 + 0] * sc;
                float vy = acc[mi][ni][half * 2 + 1] * sc;
                if (rv && cv) {
                    float2 o; o.x = vx; o.y = vy;
                    *reinterpret_cast<float2*>(dst + lcol) = o;
                }
                float ex = (rv && cv) ? expf(vx) : 0.f;
                float ey = (rv && cv) ? expf(vy) : 0.f;
                rowsum[mi][half] += ex + ey;
                colsum[ni][0] += ex;
                colsum[ni][1] += ey;
            }
        }
    }
    #pragma unroll
    for (int mi = 0; mi < 4; mi++) {
        #pragma unroll
        for (int half = 0; half < 2; half++) {
            float r = rowsum[mi][half];
            r += __shfl_xor_sync(0xffffffffu, r, 1);
            r += __shfl_xor_sync(0xffffffffu, r, 2);
            if ((lane & 3) == 0) {
                int lrow = warp_m * 64 + mi * 16 + half * 8 + qrow;
                if (lrow < mrem) atomicAdd(&g_rsum[b * LD + m0 + lrow], r);
            }
        }
    }
    #pragma unroll
    for (int ni = 0; ni < 4; ni++) {
        #pragma unroll
        for (int c = 0; c < 2; c++) {
            float v = colsum[ni][c];
            v += __shfl_xor_sync(0xffffffffu, v, 4);
            v += __shfl_xor_sync(0xffffffffu, v, 8);
            v += __shfl_xor_sync(0xffffffffu, v, 16);
            if (lane < 4) {
                int lcol = warp_n * 32 + ni * 8 + qcol + c;
                if (lcol < nrem) atomicAdd(&g_csum[b * SD + n0 + lcol], v);
            }
        }
    }
}

// conf = exp(2*sim)/(rsum*csum); smem cinv + smem colmax, int atomics for maxes
#define CROWS 16
#define NV4 (SD / 4)              // 1200 float4 per row
__global__ void __launch_bounds__(256) k_conf(float* __restrict__ conf) {
    __shared__ float4 s_cinv[NV4];    // 19.2 KB
    __shared__ float4 s_cmax[NV4];    // 19.2 KB
    const int r0 = blockIdx.x * CROWS;
    const int n = r0 / LD;
    const int tid = threadIdx.x;

    // load column-sum inverses, zero colmax
    for (int i = tid; i < NV4; i += 256) {
        float4 cs = *reinterpret_cast<const float4*>(&g_csum[n * SD + i * 4]);
        float4 ci;
        ci.x = 1.f / cs.x; ci.y = 1.f / cs.y; ci.z = 1.f / cs.z; ci.w = 1.f / cs.w;
        s_cinv[i] = ci;
        s_cmax[i] = make_float4(0.f, 0.f, 0.f, 0.f);
    }
    __syncthreads();

    for (int rr = 0; rr < CROWS; rr++) {
        const int row = r0 + rr;
        const float inv_rs = 1.f / g_rsum[row];
        const float4* sv = reinterpret_cast<const float4*>(g_sim + (size_t)row * SD);
        float4* cv = reinterpret_cast<float4*>(conf + (size_t)row * SD);
        float rcm = 0.f;
        #pragma unroll
        for (int w = 0; w < 5; w++) {
            int i = tid + w * 256;
            if (i < NV4) {
                float4 s4 = sv[i];
                float4 ci = s_cinv[i];
                float4 c4;
                c4.x = expf(2.f * s4.x) * inv_rs * ci.x;
                c4.y = expf(2.f * s4.y) * inv_rs * ci.y;
                c4.z = expf(2.f * s4.z) * inv_rs * ci.z;
                c4.w = expf(2.f * s4.w) * inv_rs * ci.w;
                cv[i] = c4;
                rcm = fmaxf(rcm, fmaxf(fmaxf(c4.x, c4.y), fmaxf(c4.z, c4.w)));
                float4 cm = s_cmax[i];           // thread-exclusive slot
                cm.x = fmaxf(cm.x, c4.x); cm.y = fmaxf(cm.y, c4.y);
                cm.z = fmaxf(cm.z, c4.z); cm.w = fmaxf(cm.w, c4.w);
                s_cmax[i] = cm;
            }
        }
        rcm = warpMaxF(rcm);
        if ((tid & 31) == 0) atomicMax(&g_rcmax[row], __float_as_int(rcm));
    }
    __syncthreads();
    // flush column maxes (positive floats: int-max == float-max)
    for (int i = tid; i < NV4; i += 256) {
        float4 cm = s_cmax[i];
        int base = n * SD + i * 4;
        atomicMax(&g_ccmax[base + 0], __float_as_int(cm.x));
        atomicMax(&g_ccmax[base + 1], __float_as_int(cm.y));
        atomicMax(&g_ccmax[base + 2], __float_as_int(cm.z));
        atomicMax(&g_ccmax[base + 3], __float_as_int(cm.w));
    }
}

// match extraction
__global__ void __launch_bounds__(256) k_match(const float* __restrict__ conf,
                                               float* __restrict__ mmask,
                                               float* __restrict__ jids,
                                               float* __restrict__ mconf,
                                               const int* __restrict__ w0p,
                                               const int* __restrict__ w1p) {
    const int row = blockIdx.x;
    const int n = row / LD;
    const int l = row % LD;
    const int w0c = *w0p;
    const int w1c = *w1p;

    const bool v0 = ((l / w0c) >= BORDER) && ((l % w0c) >= BORDER);
    const float rm = __int_as_float(g_rcmax[row]);
    const float* crow = conf + (size_t)row * SD;

    int best = 0x7fffffff;
    if (v0 && rm > THRESH) {
        for (int s = threadIdx.x; s < SD; s += 256) {
            float c = crow[s];
            if (c > THRESH && c == rm && c == __int_as_float(g_ccmax[n * SD + s])) {
                if (((s / w1c) >= BORDER) && ((s % w1c) >= BORDER)) best = min(best, s);
            }
        }
    }
    __shared__ int ired[8];
    int wmin = warpMinI(best);
    if ((threadIdx.x & 31) == 0) ired[threadIdx.x >> 5] = wmin;
    __syncthreads();
    if (threadIdx.x == 0) {
        int bmin = 0x7fffffff;
        #pragma unroll
        for (int i = 0; i < 8; i++) bmin = min(bmin, ired[i]);
        bool match = (bmin != 0x7fffffff);
        int j = match ? bmin : 0;
        mmask[row] = match ? 1.f : 0.f;
        jids[row]  = (float)j;
        mconf[row] = match ? crow[j] : 0.f;
    }
}

// ---------------- launch ----------------
extern "C" void kernel_launch(void* const* d_in, const int* in_sizes, int n_in,
                              void* d_out, int out_size) {
    const float* f0 = (const float*)d_in[0];
    const float* f1 = (const float*)d_in[1];
    const int* w0 = (const int*)d_in[3];
    const int* w1 = (const int*)d_in[5];

    float* out = (float*)d_out;
    float* conf = out;
    const size_t NLS = (size_t)NB * LD * SD;
    float* mm = out + NLS;
    float* jj = mm + NB * LD;
    float* mc = jj + NB * LD;

    static int cfg_done = 0;
    if (!cfg_done) {
        cudaFuncSetAttribute(k_gemm_mma, cudaFuncAttributeMaxDynamicSharedMemorySize, DSMEM_B);
        cfg_done = 1;
    }

    k_init<<<(NB * SD + 255) / 256, 256>>>();
    k_convert<<<(NB * LD * CD + 255) / 256, 256>>>(f0, f1);
    dim3 gg((SD + TN - 1) / TN, (LD + TM - 1) / TM, NB);
    k_gemm_mma<<<gg, 256, DSMEM_B>>>();
    k_conf<<<NB * LD / CROWS, 256>>>(conf);
    k_match<<<NB * LD, 256>>>(conf, mm, jj, mc, w0, w1);
}